// round 10
// baseline (speedup 1.0000x reference)
#include <cuda_runtime.h>
#include <cstdint>

#define G_N   2048
#define HID   128
#define NMAX  100000
#define EMAX  600000

// ---------------- scratch (static device globals; no allocations) -------------
static __device__ __align__(16) int   d_deg[NMAX];
static __device__ __align__(16) int   d_rowptr[NMAX + 1];
static __device__ __align__(16) int   d_woff[NMAX];
static __device__ __align__(16) int   d_csrsrc[EMAX];
static __device__ __align__(16) int   d_gstart[G_N + 1];
static __device__ __align__(16) float d_z8[(size_t)NMAX * 8];
static __device__ __align__(16) float d_h1[(size_t)NMAX * HID];
static __device__ __align__(16) float d_h2[(size_t)NMAX * HID];
static __device__ __align__(16) float d_h3[(size_t)NMAX * HID];
static __device__ __align__(16) float d_zbuf[(size_t)NMAX * HID];
static __device__ __align__(16) float d_pooled[(size_t)G_N * 384];
static __device__ __align__(16) float d_grow[(size_t)G_N * HID];
static __device__ __align__(16) float d_zc[(size_t)G_N * HID];
static __device__ __align__(16) float d_mu[HID];
static __device__ __align__(16) float d_rstd[HID];

// ---------------- CSR build ---------------------------------------------------
__global__ void k_clear_deg(int N) {
    int i = blockIdx.x * blockDim.x + threadIdx.x;
    if (i < N) d_deg[i] = 0;
}

__global__ void k_hist(const int* __restrict__ dst, int E) {
    int i = blockIdx.x * blockDim.x + threadIdx.x;
    if (i < E) atomicAdd(&d_deg[dst[i]], 1);
}

__global__ void k_scan(int N, int E) {
    __shared__ int part[1024];
    int tid = threadIdx.x;
    int chunk = (N + 1023) / 1024;
    int beg = tid * chunk;
    int end = min(beg + chunk, N);
    int s = 0;
    for (int i = beg; i < end; i++) s += d_deg[i];
    part[tid] = s;
    __syncthreads();
    for (int off = 1; off < 1024; off <<= 1) {
        int v = (tid >= off) ? part[tid - off] : 0;
        __syncthreads();
        part[tid] += v;
        __syncthreads();
    }
    int run = (tid == 0) ? 0 : part[tid - 1];
    for (int i = beg; i < end; i++) {
        d_rowptr[i] = run;
        d_woff[i] = run;
        run += d_deg[i];
    }
    if (tid == 1023) d_rowptr[N] = E;
}

__global__ void k_fill(const int* __restrict__ src, const int* __restrict__ dst, int E) {
    int i = blockIdx.x * blockDim.x + threadIdx.x;
    if (i < E) {
        int p = atomicAdd(&d_woff[dst[i]], 1);
        d_csrsrc[p] = src[i];
    }
}

__global__ void k_gstart(const int* __restrict__ batch, int N) {
    int n = blockIdx.x * blockDim.x + threadIdx.x;
    if (n >= N) return;
    int b = batch[n];
    int bp = (n == 0) ? -1 : batch[n - 1];
    for (int g = bp + 1; g <= b; g++) d_gstart[g] = n;
    if (n == N - 1)
        for (int g = b + 1; g <= G_N; g++) d_gstart[g] = N;
}

// ---------------- aggregation -------------------------------------------------
__global__ void k_agg7(const float* __restrict__ x, int N) {
    int n = blockIdx.x * blockDim.x + threadIdx.x;
    if (n >= N) return;
    float a[8];
#pragma unroll
    for (int j = 0; j < 7; j++) a[j] = x[n * 7 + j];
    a[7] = 0.f;
    int b = d_rowptr[n], e = d_rowptr[n + 1];
    for (int i = b; i < e; i++) {
        int s = d_csrsrc[i];
#pragma unroll
        for (int j = 0; j < 7; j++) a[j] += x[s * 7 + j];
    }
#pragma unroll
    for (int j = 0; j < 8; j++) d_z8[(size_t)n * 8 + j] = a[j];
}

__global__ void k_agg128(const float* __restrict__ h, float* __restrict__ z, int N) {
    int w = (blockIdx.x * blockDim.x + threadIdx.x) >> 5;
    int lane = threadIdx.x & 31;
    if (w >= N) return;
    const float4* hv = (const float4*)h;
    float4 acc = hv[(size_t)w * 32 + lane];
    int b = d_rowptr[w], e = d_rowptr[w + 1];
    for (int i = b; i < e; i++) {
        int s = d_csrsrc[i];
        float4 v = hv[(size_t)s * 32 + lane];
        acc.x += v.x; acc.y += v.y; acc.z += v.z; acc.w += v.w;
    }
    ((float4*)z)[(size_t)w * 32 + lane] = acc;
}

// ================= TF32 mma.sync fused 2-layer MLP =============================
// out = relu( relu(A @ W1 + b1) @ W2 + b2 )
// A: [N, lda] fp32 (lda = 8 or 128); W1: [kw1, 128]; W2: [128, 128]
// Legacy tensor-core path (mma.sync m16n8k8 tf32) — compiles at compute_103.
// Persistent CTAs, 256 threads (8 warps, 4x2), tile M=128 x N=128.
// smem: A/Y tile pitch 132 (A-frag conflict-free), W pitch 136 (B-frag conflict-free)

#define PA 132
#define PW 136
#define SM_A  0
#define SM_W1 (128 * PA * 4)                    // 67584
#define SM_W2 (SM_W1 + 128 * PW * 4)            // 137216
#define MMA_SMEM (SM_W2 + 128 * PW * 4)         // 206848

__device__ __forceinline__ uint32_t f2tf32(float f) {
    uint32_t r;
    asm("cvt.rna.tf32.f32 %0, %1;" : "=r"(r) : "f"(f));
    return r;
}
__device__ __forceinline__ void mma8(float* c, const uint32_t* a, const uint32_t* b) {
    asm volatile(
        "mma.sync.aligned.m16n8k8.row.col.f32.tf32.tf32.f32 "
        "{%0,%1,%2,%3}, {%4,%5,%6,%7}, {%8,%9}, {%0,%1,%2,%3};"
        : "+f"(c[0]), "+f"(c[1]), "+f"(c[2]), "+f"(c[3])
        : "r"(a[0]), "r"(a[1]), "r"(a[2]), "r"(a[3]), "r"(b[0]), "r"(b[1]));
}

__global__ __launch_bounds__(256, 1)
void k_mma_mlp(const float* __restrict__ A, int lda, int q4s, int N, int ks1,
               const float* __restrict__ W1, int kw1,
               const float* __restrict__ b1,
               const float* __restrict__ W2,
               const float* __restrict__ b2,
               float* __restrict__ out) {
    extern __shared__ char dsm[];
    float*    sA  = (float*)(dsm + SM_A);
    uint32_t* sAu = (uint32_t*)(dsm + SM_A);
    uint32_t* sW1u = (uint32_t*)(dsm + SM_W1);
    uint32_t* sW2u = (uint32_t*)(dsm + SM_W2);
    __shared__ float sb1[128], sb2[128];

    int tid = threadIdx.x;
    int wid = tid >> 5, lane = tid & 31;
    int g = lane >> 2, t = lane & 3;            // groupID, threadID-in-group
    int wr = wid & 3, wc = wid >> 2;            // warp row (4), warp col (2)
    int r0 = wr * 32;                           // warp's row base (2 m16 tiles)
    int n0 = wc * 64;                           // warp's col base (8 n8 tiles)

    if (tid < 128) { sb1[tid] = b1[tid]; sb2[tid] = b2[tid]; }

    // W1 -> smem [k][n] pitch PW, tf32, zero-pad rows k >= kw1
    for (int idx = tid; idx < ks1 * 8 * 32; idx += 256) {
        int k = idx >> 5, c4 = (idx & 31) << 2;
        float4 v = make_float4(0.f, 0.f, 0.f, 0.f);
        if (k < kw1) v = *(const float4*)&W1[k * HID + c4];
        uint4 u = make_uint4(f2tf32(v.x), f2tf32(v.y), f2tf32(v.z), f2tf32(v.w));
        *(uint4*)&sW1u[k * PW + c4] = u;
    }
    // W2 -> smem [k][n] pitch PW, tf32
    for (int idx = tid; idx < 4096; idx += 256) {
        int k = idx >> 5, c4 = (idx & 31) << 2;
        float4 v = *(const float4*)&W2[k * HID + c4];
        uint4 u = make_uint4(f2tf32(v.x), f2tf32(v.y), f2tf32(v.z), f2tf32(v.w));
        *(uint4*)&sW2u[k * PW + c4] = u;
    }
    __syncthreads();

    int ntiles = (N + 127) >> 7;
    float acc[2][8][4];

    for (int tile = blockIdx.x; tile < ntiles; tile += gridDim.x) {
        int m0 = tile << 7;

        // ---- load A tile (tf32) into pitch-PA smem ----
        int niter = 128 << q4s;
        for (int idx = tid; idx < niter; idx += 256) {
            int r = idx >> q4s, q = idx & ((1 << q4s) - 1);
            int c = q << 2;
            int n = m0 + r;
            uint4 u = make_uint4(0u, 0u, 0u, 0u);
            if (n < N) {
                float4 f = *(const float4*)&A[(size_t)n * lda + c];
                u = make_uint4(f2tf32(f.x), f2tf32(f.y), f2tf32(f.z), f2tf32(f.w));
            }
            *(uint4*)&sAu[r * PA + c] = u;
        }
        __syncthreads();

        // ---- GEMM1: D1 = A @ W1 ----
#pragma unroll
        for (int mt = 0; mt < 2; mt++)
#pragma unroll
            for (int nt = 0; nt < 8; nt++)
#pragma unroll
                for (int j = 0; j < 4; j++) acc[mt][nt][j] = 0.f;

        for (int k = 0; k < ks1; k++) {
            int k0 = k << 3;
            uint32_t a[2][4];
#pragma unroll
            for (int mt = 0; mt < 2; mt++) {
                int rb = (r0 + mt * 16 + g) * PA + k0 + t;
                a[mt][0] = sAu[rb];
                a[mt][1] = sAu[rb + 8 * PA];
                a[mt][2] = sAu[rb + 4];
                a[mt][3] = sAu[rb + 8 * PA + 4];
            }
            uint32_t b[8][2];
#pragma unroll
            for (int nt = 0; nt < 8; nt++) {
                int wb = (k0 + t) * PW + n0 + nt * 8 + g;
                b[nt][0] = sW1u[wb];
                b[nt][1] = sW1u[wb + 4 * PW];
            }
#pragma unroll
            for (int mt = 0; mt < 2; mt++)
#pragma unroll
                for (int nt = 0; nt < 8; nt++)
                    mma8(acc[mt][nt], a[mt], b[nt]);
        }
        __syncthreads();  // A-tile reads done before Y overwrites

        // ---- epilogue 1: Y = tf32(relu(D1 + b1)) -> A buffer ----
#pragma unroll
        for (int mt = 0; mt < 2; mt++) {
            int r = r0 + mt * 16 + g;
#pragma unroll
            for (int nt = 0; nt < 8; nt++) {
                int c = n0 + nt * 8 + 2 * t;
                sAu[r * PA + c]           = f2tf32(fmaxf(acc[mt][nt][0] + sb1[c], 0.f));
                sAu[r * PA + c + 1]       = f2tf32(fmaxf(acc[mt][nt][1] + sb1[c + 1], 0.f));
                sAu[(r + 8) * PA + c]     = f2tf32(fmaxf(acc[mt][nt][2] + sb1[c], 0.f));
                sAu[(r + 8) * PA + c + 1] = f2tf32(fmaxf(acc[mt][nt][3] + sb1[c + 1], 0.f));
            }
        }
        __syncthreads();

        // ---- GEMM2: D2 = Y @ W2 (K = 128) ----
#pragma unroll
        for (int mt = 0; mt < 2; mt++)
#pragma unroll
            for (int nt = 0; nt < 8; nt++)
#pragma unroll
                for (int j = 0; j < 4; j++) acc[mt][nt][j] = 0.f;

        for (int k = 0; k < 16; k++) {
            int k0 = k << 3;
            uint32_t a[2][4];
#pragma unroll
            for (int mt = 0; mt < 2; mt++) {
                int rb = (r0 + mt * 16 + g) * PA + k0 + t;
                a[mt][0] = sAu[rb];
                a[mt][1] = sAu[rb + 8 * PA];
                a[mt][2] = sAu[rb + 4];
                a[mt][3] = sAu[rb + 8 * PA + 4];
            }
            uint32_t b[8][2];
#pragma unroll
            for (int nt = 0; nt < 8; nt++) {
                int wb = (k0 + t) * PW + n0 + nt * 8 + g;
                b[nt][0] = sW2u[wb];
                b[nt][1] = sW2u[wb + 4 * PW];
            }
#pragma unroll
            for (int mt = 0; mt < 2; mt++)
#pragma unroll
                for (int nt = 0; nt < 8; nt++)
                    mma8(acc[mt][nt], a[mt], b[nt]);
        }
        __syncthreads();  // Y reads done before staging overwrites

        // ---- epilogue 2: relu(D2 + b2) -> staging (fp32) ----
#pragma unroll
        for (int mt = 0; mt < 2; mt++) {
            int r = r0 + mt * 16 + g;
#pragma unroll
            for (int nt = 0; nt < 8; nt++) {
                int c = n0 + nt * 8 + 2 * t;
                sA[r * PA + c]           = fmaxf(acc[mt][nt][0] + sb2[c], 0.f);
                sA[r * PA + c + 1]       = fmaxf(acc[mt][nt][1] + sb2[c + 1], 0.f);
                sA[(r + 8) * PA + c]     = fmaxf(acc[mt][nt][2] + sb2[c], 0.f);
                sA[(r + 8) * PA + c + 1] = fmaxf(acc[mt][nt][3] + sb2[c + 1], 0.f);
            }
        }
        __syncthreads();

        // ---- coalesced store to gmem ----
        for (int idx = tid; idx < 4096; idx += 256) {
            int r = idx >> 5, q = idx & 31;
            int n = m0 + r;
            if (n < N)
                *(float4*)&out[(size_t)n * HID + (q << 2)] =
                    *(const float4*)&sA[r * PA + (q << 2)];
        }
        __syncthreads();  // protect A buffer for next tile
    }
}

// ---------------- pooling + classifier ----------------------------------------
__global__ void k_pool(const float* __restrict__ h1, const float* __restrict__ h2,
                       const float* __restrict__ h3) {
    int g = blockIdx.x, c = threadIdx.x;  // 128 threads
    int s = d_gstart[g], e = d_gstart[g + 1];
    float a1 = 0.f, a2 = 0.f, a3 = 0.f;
    for (int r = s; r < e; r++) {
        a1 += h1[(size_t)r * HID + c];
        a2 += h2[(size_t)r * HID + c];
        a3 += h3[(size_t)r * HID + c];
    }
    d_pooled[(size_t)g * 384 + c] = a1;
    d_pooled[(size_t)g * 384 + 128 + c] = a2;
    d_pooled[(size_t)g * 384 + 256 + c] = a3;
}

__global__ void k_smallmm(const float* __restrict__ in, int K,
                          const float* __restrict__ w, const float* __restrict__ b,
                          int useCnt, float* __restrict__ out) {
    __shared__ float sp[8 * 384];
    int g0 = blockIdx.x * 8;
    int tid = threadIdx.x;  // 128
    for (int i = tid; i < 8 * K; i += 128) sp[i] = in[(size_t)g0 * K + i];
    __syncthreads();
    int c = tid;
    float acc[8] = {0.f, 0.f, 0.f, 0.f, 0.f, 0.f, 0.f, 0.f};
    for (int k = 0; k < K; k++) {
        float wv = w[k * HID + c];
#pragma unroll
        for (int j = 0; j < 8; j++) acc[j] += sp[j * K + k] * wv;
    }
    float bv = b[c];
#pragma unroll
    for (int j = 0; j < 8; j++) {
        int g = g0 + j;
        float scale = useCnt ? (float)(d_gstart[g + 1] - d_gstart[g]) : 1.f;
        out[(size_t)g * HID + c] = acc[j] + scale * bv;
    }
}

__global__ void k_bn() {
    __shared__ double ss[256], sq[256];
    int col = blockIdx.x, tid = threadIdx.x;
    double s = 0.0, q = 0.0;
    for (int r = tid; r < G_N; r += 256) {
        double v = (double)d_zc[(size_t)r * HID + col];
        s += v; q += v * v;
    }
    ss[tid] = s; sq[tid] = q;
    __syncthreads();
    for (int off = 128; off; off >>= 1) {
        if (tid < off) { ss[tid] += ss[tid + off]; sq[tid] += sq[tid + off]; }
        __syncthreads();
    }
    if (tid == 0) {
        double mu = ss[0] / G_N;
        double var = sq[0] / G_N - mu * mu;
        d_mu[col] = (float)mu;
        d_rstd[col] = (float)(1.0 / sqrt(var + 1e-5));
    }
}

__global__ void k_final(const float* __restrict__ bn_g, const float* __restrict__ bn_b,
                        const float* __restrict__ c2_w, const float* __restrict__ c2_b,
                        float* __restrict__ out) {
    __shared__ float r0s[128], r1s[128];
    int g = blockIdx.x, c = threadIdx.x;
    float z = (d_zc[(size_t)g * HID + c] - d_mu[c]) * d_rstd[c] * bn_g[c] + bn_b[c];
    z = fmaxf(z, 0.f);
    r0s[c] = z * c2_w[c * 2 + 0];
    r1s[c] = z * c2_w[c * 2 + 1];
    __syncthreads();
    for (int off = 64; off; off >>= 1) {
        if (c < off) { r0s[c] += r0s[c + off]; r1s[c] += r1s[c + off]; }
        __syncthreads();
    }
    if (c == 0) {
        out[g * 2 + 0] = r0s[0] + c2_b[0];
        out[g * 2 + 1] = r1s[0] + c2_b[1];
    }
}

// ---------------- host orchestration ------------------------------------------
extern "C" void kernel_launch(void* const* d_in, const int* in_sizes, int n_in,
                              void* d_out, int out_size) {
    const float* x     = (const float*)d_in[0];
    const int*   ei    = (const int*)d_in[1];
    const int*   batch = (const int*)d_in[3];
    const float* g1_w1 = (const float*)d_in[4];
    const float* g1_b1 = (const float*)d_in[5];
    const float* g1_w2 = (const float*)d_in[6];
    const float* g1_b2 = (const float*)d_in[7];
    const float* g2_w1 = (const float*)d_in[8];
    const float* g2_b1 = (const float*)d_in[9];
    const float* g2_w2 = (const float*)d_in[10];
    const float* g2_b2 = (const float*)d_in[11];
    const float* g3_w1 = (const float*)d_in[12];
    const float* g3_b1 = (const float*)d_in[13];
    const float* g3_w2 = (const float*)d_in[14];
    const float* g3_b2 = (const float*)d_in[15];
    const float* jk_w  = (const float*)d_in[16];
    const float* jk_b  = (const float*)d_in[17];
    const float* c1_w  = (const float*)d_in[18];
    const float* c1_b  = (const float*)d_in[19];
    const float* bn_g  = (const float*)d_in[20];
    const float* bn_b  = (const float*)d_in[21];
    const float* c2_w  = (const float*)d_in[22];
    const float* c2_b  = (const float*)d_in[23];
    float* out = (float*)d_out;

    int N = in_sizes[0] / 7;
    int E = in_sizes[1] / 2;
    const int* src = ei;
    const int* dst = ei + E;

    cudaFuncSetAttribute(k_mma_mlp, cudaFuncAttributeMaxDynamicSharedMemorySize, MMA_SMEM);

    // resolve true DEVICE addresses of __device__ globals (round-4 lesson)
    float *p_z8, *p_h1, *p_h2, *p_h3, *p_zbuf, *p_pooled, *p_grow, *p_zc;
    cudaGetSymbolAddress((void**)&p_z8,     d_z8);
    cudaGetSymbolAddress((void**)&p_h1,     d_h1);
    cudaGetSymbolAddress((void**)&p_h2,     d_h2);
    cudaGetSymbolAddress((void**)&p_h3,     d_h3);
    cudaGetSymbolAddress((void**)&p_zbuf,   d_zbuf);
    cudaGetSymbolAddress((void**)&p_pooled, d_pooled);
    cudaGetSymbolAddress((void**)&p_grow,   d_grow);
    cudaGetSymbolAddress((void**)&p_zc,     d_zc);

    int nb256 = (N + 255) / 256;
    int eb256 = (E + 255) / 256;

    // CSR build + graph boundaries
    k_clear_deg<<<nb256, 256>>>(N);
    k_hist<<<eb256, 256>>>(dst, E);
    k_scan<<<1, 1024>>>(N, E);
    k_fill<<<eb256, 256>>>(src, dst, E);
    k_gstart<<<nb256, 256>>>(batch, N);

    // conv1: 7-dim aggregation then TF32 tensor-core fused MLP
    k_agg7<<<nb256, 256>>>(x, N);
    k_mma_mlp<<<148, 256, MMA_SMEM>>>(p_z8, 8, 1, N, 1,
                                      g1_w1, 7, g1_b1, g1_w2, g1_b2, p_h1);
    // conv2
    k_agg128<<<(N + 7) / 8, 256>>>(p_h1, p_zbuf, N);
    k_mma_mlp<<<148, 256, MMA_SMEM>>>(p_zbuf, HID, 5, N, 16,
                                      g2_w1, 128, g2_b1, g2_w2, g2_b2, p_h2);
    // conv3
    k_agg128<<<(N + 7) / 8, 256>>>(p_h2, p_zbuf, N);
    k_mma_mlp<<<148, 256, MMA_SMEM>>>(p_zbuf, HID, 5, N, 16,
                                      g3_w1, 128, g3_b1, g3_w2, g3_b2, p_h3);

    // pool-first JK: segment_sum then tiny GEMMs
    k_pool<<<G_N, 128>>>(p_h1, p_h2, p_h3);
    k_smallmm<<<G_N / 8, 128>>>(p_pooled, 384, jk_w, jk_b, 1, p_grow);
    k_smallmm<<<G_N / 8, 128>>>(p_grow, 128, c1_w, c1_b, 0, p_zc);

    // batch norm + classifier head
    k_bn<<<HID, 256>>>();
    k_final<<<G_N, 128>>>(bn_g, bn_b, c2_w, c2_b, out);
}

// round 11
// speedup vs baseline: 1.4044x; 1.4044x over previous
#include <cuda_runtime.h>
#include <cstdint>

#define G_N   2048
#define HID   128
#define NMAX  100000
#define EMAX  600000

// ---------------- scratch (static device globals; no allocations) -------------
static __device__ __align__(16) int   d_deg[NMAX];
static __device__ __align__(16) int   d_rowptr[NMAX + 1];
static __device__ __align__(16) int   d_woff[NMAX];
static __device__ __align__(16) int   d_csrsrc[EMAX];
static __device__ __align__(16) int   d_gstart[G_N + 1];
static __device__ __align__(16) float d_z8[(size_t)NMAX * 8];
static __device__ __align__(16) float d_h1[(size_t)NMAX * HID];
static __device__ __align__(16) float d_h2[(size_t)NMAX * HID];
static __device__ __align__(16) float d_h3[(size_t)NMAX * HID];
static __device__ __align__(16) float d_zbuf[(size_t)NMAX * HID];
static __device__ __align__(16) float d_pooled[(size_t)G_N * 384];
static __device__ __align__(16) float d_grow[(size_t)G_N * HID];
static __device__ __align__(16) float d_zc[(size_t)G_N * HID];
static __device__ __align__(16) float d_mu[HID];
static __device__ __align__(16) float d_rstd[HID];

// ---------------- CSR build ---------------------------------------------------
__global__ void k_clear_deg(int N) {
    int i = blockIdx.x * blockDim.x + threadIdx.x;
    if (i < N) d_deg[i] = 0;
}

__global__ void k_hist(const int* __restrict__ dst, int E) {
    int i = blockIdx.x * blockDim.x + threadIdx.x;
    if (i < E) atomicAdd(&d_deg[dst[i]], 1);
}

__global__ void k_scan(int N, int E) {
    __shared__ int part[1024];
    int tid = threadIdx.x;
    int chunk = (N + 1023) / 1024;
    int beg = tid * chunk;
    int end = min(beg + chunk, N);
    int s = 0;
    for (int i = beg; i < end; i++) s += d_deg[i];
    part[tid] = s;
    __syncthreads();
    for (int off = 1; off < 1024; off <<= 1) {
        int v = (tid >= off) ? part[tid - off] : 0;
        __syncthreads();
        part[tid] += v;
        __syncthreads();
    }
    int run = (tid == 0) ? 0 : part[tid - 1];
    for (int i = beg; i < end; i++) {
        d_rowptr[i] = run;
        d_woff[i] = run;
        run += d_deg[i];
    }
    if (tid == 1023) d_rowptr[N] = E;
}

__global__ void k_fill(const int* __restrict__ src, const int* __restrict__ dst, int E) {
    int i = blockIdx.x * blockDim.x + threadIdx.x;
    if (i < E) {
        int p = atomicAdd(&d_woff[dst[i]], 1);
        d_csrsrc[p] = src[i];
    }
}

__global__ void k_gstart(const int* __restrict__ batch, int N) {
    int n = blockIdx.x * blockDim.x + threadIdx.x;
    if (n >= N) return;
    int b = batch[n];
    int bp = (n == 0) ? -1 : batch[n - 1];
    for (int g = bp + 1; g <= b; g++) d_gstart[g] = n;
    if (n == N - 1)
        for (int g = b + 1; g <= G_N; g++) d_gstart[g] = N;
}

// ---------------- aggregation -------------------------------------------------
__global__ void k_agg7(const float* __restrict__ x, int N) {
    int n = blockIdx.x * blockDim.x + threadIdx.x;
    if (n >= N) return;
    float a[8];
#pragma unroll
    for (int j = 0; j < 7; j++) a[j] = x[n * 7 + j];
    a[7] = 0.f;
    int b = d_rowptr[n], e = d_rowptr[n + 1];
    for (int i = b; i < e; i++) {
        int s = d_csrsrc[i];
#pragma unroll
        for (int j = 0; j < 7; j++) a[j] += x[s * 7 + j];
    }
#pragma unroll
    for (int j = 0; j < 8; j++) d_z8[(size_t)n * 8 + j] = a[j];
}

__global__ void k_agg128(const float* __restrict__ h, float* __restrict__ z, int N) {
    int w = (blockIdx.x * blockDim.x + threadIdx.x) >> 5;
    int lane = threadIdx.x & 31;
    if (w >= N) return;
    const float4* hv = (const float4*)h;
    float4 acc = hv[(size_t)w * 32 + lane];
    int b = d_rowptr[w], e = d_rowptr[w + 1];
    for (int i = b; i < e; i++) {
        int s = d_csrsrc[i];
        float4 v = hv[(size_t)s * 32 + lane];
        acc.x += v.x; acc.y += v.y; acc.z += v.z; acc.w += v.w;
    }
    ((float4*)z)[(size_t)w * 32 + lane] = acc;
}

// ================= TF32 mma.sync fused 2-layer MLP =============================
// out = relu( relu(A @ W1 + b1) @ W2 + b2 )
// A: [N, lda] fp32 (lda = 8 or 128); W1: [kw1, 128]; W2: [128, 128]
// Legacy tensor-core path (mma.sync m16n8k8 tf32) — compiles at compute_103.
// Persistent CTAs, 256 threads (8 warps, 4x2), tile M=128 x N=128.
// smem: A/Y tile pitch 132 (A-frag conflict-free), W pitch 136 (B-frag conflict-free)

#define PA 132
#define PW 136
#define SM_A  0
#define SM_W1 (128 * PA * 4)                    // 67584
#define SM_W2 (SM_W1 + 128 * PW * 4)            // 137216
#define MMA_SMEM (SM_W2 + 128 * PW * 4)         // 206848

__device__ __forceinline__ uint32_t f2tf32(float f) {
    uint32_t r;
    asm("cvt.rna.tf32.f32 %0, %1;" : "=r"(r) : "f"(f));
    return r;
}
__device__ __forceinline__ void mma8(float* c, const uint32_t* a, const uint32_t* b) {
    asm volatile(
        "mma.sync.aligned.m16n8k8.row.col.f32.tf32.tf32.f32 "
        "{%0,%1,%2,%3}, {%4,%5,%6,%7}, {%8,%9}, {%0,%1,%2,%3};"
        : "+f"(c[0]), "+f"(c[1]), "+f"(c[2]), "+f"(c[3])
        : "r"(a[0]), "r"(a[1]), "r"(a[2]), "r"(a[3]), "r"(b[0]), "r"(b[1]));
}

__global__ __launch_bounds__(256, 1)
void k_mma_mlp(const float* __restrict__ A, int lda, int q4s, int N, int ks1,
               const float* __restrict__ W1, int kw1,
               const float* __restrict__ b1,
               const float* __restrict__ W2,
               const float* __restrict__ b2,
               float* __restrict__ out) {
    extern __shared__ char dsm[];
    float*    sA  = (float*)(dsm + SM_A);
    uint32_t* sAu = (uint32_t*)(dsm + SM_A);
    uint32_t* sW1u = (uint32_t*)(dsm + SM_W1);
    uint32_t* sW2u = (uint32_t*)(dsm + SM_W2);
    __shared__ float sb1[128], sb2[128];

    int tid = threadIdx.x;
    int wid = tid >> 5, lane = tid & 31;
    int g = lane >> 2, t = lane & 3;            // groupID, threadID-in-group
    int wr = wid & 3, wc = wid >> 2;            // warp row (4), warp col (2)
    int r0 = wr * 32;                           // warp's row base (2 m16 tiles)
    int n0 = wc * 64;                           // warp's col base (8 n8 tiles)

    if (tid < 128) { sb1[tid] = b1[tid]; sb2[tid] = b2[tid]; }

    // W1 -> smem [k][n] pitch PW, tf32, zero-pad rows k >= kw1
    for (int idx = tid; idx < ks1 * 8 * 32; idx += 256) {
        int k = idx >> 5, c4 = (idx & 31) << 2;
        float4 v = make_float4(0.f, 0.f, 0.f, 0.f);
        if (k < kw1) v = *(const float4*)&W1[k * HID + c4];
        uint4 u = make_uint4(f2tf32(v.x), f2tf32(v.y), f2tf32(v.z), f2tf32(v.w));
        *(uint4*)&sW1u[k * PW + c4] = u;
    }
    // W2 -> smem [k][n] pitch PW, tf32
    for (int idx = tid; idx < 4096; idx += 256) {
        int k = idx >> 5, c4 = (idx & 31) << 2;
        float4 v = *(const float4*)&W2[k * HID + c4];
        uint4 u = make_uint4(f2tf32(v.x), f2tf32(v.y), f2tf32(v.z), f2tf32(v.w));
        *(uint4*)&sW2u[k * PW + c4] = u;
    }
    __syncthreads();

    int ntiles = (N + 127) >> 7;
    float acc[2][8][4];

    for (int tile = blockIdx.x; tile < ntiles; tile += gridDim.x) {
        int m0 = tile << 7;

        // ---- load A tile (tf32) into pitch-PA smem ----
        int niter = 128 << q4s;
        for (int idx = tid; idx < niter; idx += 256) {
            int r = idx >> q4s, q = idx & ((1 << q4s) - 1);
            int c = q << 2;
            int n = m0 + r;
            uint4 u = make_uint4(0u, 0u, 0u, 0u);
            if (n < N) {
                float4 f = *(const float4*)&A[(size_t)n * lda + c];
                u = make_uint4(f2tf32(f.x), f2tf32(f.y), f2tf32(f.z), f2tf32(f.w));
            }
            *(uint4*)&sAu[r * PA + c] = u;
        }
        __syncthreads();

        // ---- GEMM1: D1 = A @ W1 ----
#pragma unroll
        for (int mt = 0; mt < 2; mt++)
#pragma unroll
            for (int nt = 0; nt < 8; nt++)
#pragma unroll
                for (int j = 0; j < 4; j++) acc[mt][nt][j] = 0.f;

        for (int k = 0; k < ks1; k++) {
            int k0 = k << 3;
            uint32_t a[2][4];
#pragma unroll
            for (int mt = 0; mt < 2; mt++) {
                int rb = (r0 + mt * 16 + g) * PA + k0 + t;
                a[mt][0] = sAu[rb];
                a[mt][1] = sAu[rb + 8 * PA];
                a[mt][2] = sAu[rb + 4];
                a[mt][3] = sAu[rb + 8 * PA + 4];
            }
            uint32_t b[8][2];
#pragma unroll
            for (int nt = 0; nt < 8; nt++) {
                int wb = (k0 + t) * PW + n0 + nt * 8 + g;
                b[nt][0] = sW1u[wb];
                b[nt][1] = sW1u[wb + 4 * PW];
            }
#pragma unroll
            for (int mt = 0; mt < 2; mt++)
#pragma unroll
                for (int nt = 0; nt < 8; nt++)
                    mma8(acc[mt][nt], a[mt], b[nt]);
        }
        __syncthreads();  // A-tile reads done before Y overwrites

        // ---- epilogue 1: Y = tf32(relu(D1 + b1)) -> A buffer ----
#pragma unroll
        for (int mt = 0; mt < 2; mt++) {
            int r = r0 + mt * 16 + g;
#pragma unroll
            for (int nt = 0; nt < 8; nt++) {
                int c = n0 + nt * 8 + 2 * t;
                sAu[r * PA + c]           = f2tf32(fmaxf(acc[mt][nt][0] + sb1[c], 0.f));
                sAu[r * PA + c + 1]       = f2tf32(fmaxf(acc[mt][nt][1] + sb1[c + 1], 0.f));
                sAu[(r + 8) * PA + c]     = f2tf32(fmaxf(acc[mt][nt][2] + sb1[c], 0.f));
                sAu[(r + 8) * PA + c + 1] = f2tf32(fmaxf(acc[mt][nt][3] + sb1[c + 1], 0.f));
            }
        }
        __syncthreads();

        // ---- GEMM2: D2 = Y @ W2 (K = 128) ----
#pragma unroll
        for (int mt = 0; mt < 2; mt++)
#pragma unroll
            for (int nt = 0; nt < 8; nt++)
#pragma unroll
                for (int j = 0; j < 4; j++) acc[mt][nt][j] = 0.f;

        for (int k = 0; k < 16; k++) {
            int k0 = k << 3;
            uint32_t a[2][4];
#pragma unroll
            for (int mt = 0; mt < 2; mt++) {
                int rb = (r0 + mt * 16 + g) * PA + k0 + t;
                a[mt][0] = sAu[rb];
                a[mt][1] = sAu[rb + 8 * PA];
                a[mt][2] = sAu[rb + 4];
                a[mt][3] = sAu[rb + 8 * PA + 4];
            }
            uint32_t b[8][2];
#pragma unroll
            for (int nt = 0; nt < 8; nt++) {
                int wb = (k0 + t) * PW + n0 + nt * 8 + g;
                b[nt][0] = sW2u[wb];
                b[nt][1] = sW2u[wb + 4 * PW];
            }
#pragma unroll
            for (int mt = 0; mt < 2; mt++)
#pragma unroll
                for (int nt = 0; nt < 8; nt++)
                    mma8(acc[mt][nt], a[mt], b[nt]);
        }
        __syncthreads();  // Y reads done before staging overwrites

        // ---- epilogue 2: relu(D2 + b2) -> staging (fp32) ----
#pragma unroll
        for (int mt = 0; mt < 2; mt++) {
            int r = r0 + mt * 16 + g;
#pragma unroll
            for (int nt = 0; nt < 8; nt++) {
                int c = n0 + nt * 8 + 2 * t;
                sA[r * PA + c]           = fmaxf(acc[mt][nt][0] + sb2[c], 0.f);
                sA[r * PA + c + 1]       = fmaxf(acc[mt][nt][1] + sb2[c + 1], 0.f);
                sA[(r + 8) * PA + c]     = fmaxf(acc[mt][nt][2] + sb2[c], 0.f);
                sA[(r + 8) * PA + c + 1] = fmaxf(acc[mt][nt][3] + sb2[c + 1], 0.f);
            }
        }
        __syncthreads();

        // ---- coalesced store to gmem ----
        for (int idx = tid; idx < 4096; idx += 256) {
            int r = idx >> 5, q = idx & 31;
            int n = m0 + r;
            if (n < N)
                *(float4*)&out[(size_t)n * HID + (q << 2)] =
                    *(const float4*)&sA[r * PA + (q << 2)];
        }
        __syncthreads();  // protect A buffer for next tile
    }
}

// ---------------- pooling + classifier ----------------------------------------
__global__ void k_pool(const float* __restrict__ h1, const float* __restrict__ h2,
                       const float* __restrict__ h3) {
    int g = blockIdx.x, c = threadIdx.x;  // 128 threads
    int s = d_gstart[g], e = d_gstart[g + 1];
    float a1 = 0.f, a2 = 0.f, a3 = 0.f;
    for (int r = s; r < e; r++) {
        a1 += h1[(size_t)r * HID + c];
        a2 += h2[(size_t)r * HID + c];
        a3 += h3[(size_t)r * HID + c];
    }
    d_pooled[(size_t)g * 384 + c] = a1;
    d_pooled[(size_t)g * 384 + 128 + c] = a2;
    d_pooled[(size_t)g * 384 + 256 + c] = a3;
}

__global__ void k_smallmm(const float* __restrict__ in, int K,
                          const float* __restrict__ w, const float* __restrict__ b,
                          int useCnt, float* __restrict__ out) {
    __shared__ float sp[8 * 384];
    int g0 = blockIdx.x * 8;
    int tid = threadIdx.x;  // 128
    for (int i = tid; i < 8 * K; i += 128) sp[i] = in[(size_t)g0 * K + i];
    __syncthreads();
    int c = tid;
    float acc[8] = {0.f, 0.f, 0.f, 0.f, 0.f, 0.f, 0.f, 0.f};
    for (int k = 0; k < K; k++) {
        float wv = w[k * HID + c];
#pragma unroll
        for (int j = 0; j < 8; j++) acc[j] += sp[j * K + k] * wv;
    }
    float bv = b[c];
#pragma unroll
    for (int j = 0; j < 8; j++) {
        int g = g0 + j;
        float scale = useCnt ? (float)(d_gstart[g + 1] - d_gstart[g]) : 1.f;
        out[(size_t)g * HID + c] = acc[j] + scale * bv;
    }
}

__global__ void k_bn() {
    __shared__ double ss[256], sq[256];
    int col = blockIdx.x, tid = threadIdx.x;
    double s = 0.0, q = 0.0;
    for (int r = tid; r < G_N; r += 256) {
        double v = (double)d_zc[(size_t)r * HID + col];
        s += v; q += v * v;
    }
    ss[tid] = s; sq[tid] = q;
    __syncthreads();
    for (int off = 128; off; off >>= 1) {
        if (tid < off) { ss[tid] += ss[tid + off]; sq[tid] += sq[tid + off]; }
        __syncthreads();
    }
    if (tid == 0) {
        double mu = ss[0] / G_N;
        double var = sq[0] / G_N - mu * mu;
        d_mu[col] = (float)mu;
        d_rstd[col] = (float)(1.0 / sqrt(var + 1e-5));
    }
}

__global__ void k_final(const float* __restrict__ bn_g, const float* __restrict__ bn_b,
                        const float* __restrict__ c2_w, const float* __restrict__ c2_b,
                        float* __restrict__ out) {
    __shared__ float r0s[128], r1s[128];
    int g = blockIdx.x, c = threadIdx.x;
    float z = (d_zc[(size_t)g * HID + c] - d_mu[c]) * d_rstd[c] * bn_g[c] + bn_b[c];
    z = fmaxf(z, 0.f);
    r0s[c] = z * c2_w[c * 2 + 0];
    r1s[c] = z * c2_w[c * 2 + 1];
    __syncthreads();
    for (int off = 64; off; off >>= 1) {
        if (c < off) { r0s[c] += r0s[c + off]; r1s[c] += r1s[c + off]; }
        __syncthreads();
    }
    if (c == 0) {
        out[g * 2 + 0] = r0s[0] + c2_b[0];
        out[g * 2 + 1] = r1s[0] + c2_b[1];
    }
}

// ---------------- host orchestration ------------------------------------------
extern "C" void kernel_launch(void* const* d_in, const int* in_sizes, int n_in,
                              void* d_out, int out_size) {
    const float* x     = (const float*)d_in[0];
    const int*   ei    = (const int*)d_in[1];
    const int*   batch = (const int*)d_in[3];
    const float* g1_w1 = (const float*)d_in[4];
    const float* g1_b1 = (const float*)d_in[5];
    const float* g1_w2 = (const float*)d_in[6];
    const float* g1_b2 = (const float*)d_in[7];
    const float* g2_w1 = (const float*)d_in[8];
    const float* g2_b1 = (const float*)d_in[9];
    const float* g2_w2 = (const float*)d_in[10];
    const float* g2_b2 = (const float*)d_in[11];
    const float* g3_w1 = (const float*)d_in[12];
    const float* g3_b1 = (const float*)d_in[13];
    const float* g3_w2 = (const float*)d_in[14];
    const float* g3_b2 = (const float*)d_in[15];
    const float* jk_w  = (const float*)d_in[16];
    const float* jk_b  = (const float*)d_in[17];
    const float* c1_w  = (const float*)d_in[18];
    const float* c1_b  = (const float*)d_in[19];
    const float* bn_g  = (const float*)d_in[20];
    const float* bn_b  = (const float*)d_in[21];
    const float* c2_w  = (const float*)d_in[22];
    const float* c2_b  = (const float*)d_in[23];
    float* out = (float*)d_out;

    int N = in_sizes[0] / 7;
    int E = in_sizes[1] / 2;
    const int* src = ei;
    const int* dst = ei + E;

    cudaFuncSetAttribute(k_mma_mlp, cudaFuncAttributeMaxDynamicSharedMemorySize, MMA_SMEM);

    // resolve true DEVICE addresses of __device__ globals (round-4 lesson)
    float *p_z8, *p_h1, *p_h2, *p_h3, *p_zbuf, *p_pooled, *p_grow, *p_zc;
    cudaGetSymbolAddress((void**)&p_z8,     d_z8);
    cudaGetSymbolAddress((void**)&p_h1,     d_h1);
    cudaGetSymbolAddress((void**)&p_h2,     d_h2);
    cudaGetSymbolAddress((void**)&p_h3,     d_h3);
    cudaGetSymbolAddress((void**)&p_zbuf,   d_zbuf);
    cudaGetSymbolAddress((void**)&p_pooled, d_pooled);
    cudaGetSymbolAddress((void**)&p_grow,   d_grow);
    cudaGetSymbolAddress((void**)&p_zc,     d_zc);

    int nb256 = (N + 255) / 256;
    int eb256 = (E + 255) / 256;

    // CSR build + graph boundaries
    k_clear_deg<<<nb256, 256>>>(N);
    k_hist<<<eb256, 256>>>(dst, E);
    k_scan<<<1, 1024>>>(N, E);
    k_fill<<<eb256, 256>>>(src, dst, E);
    k_gstart<<<nb256, 256>>>(batch, N);

    // conv1: 7-dim aggregation then TF32 tensor-core fused MLP
    k_agg7<<<nb256, 256>>>(x, N);
    k_mma_mlp<<<148, 256, MMA_SMEM>>>(p_z8, 8, 1, N, 1,
                                      g1_w1, 7, g1_b1, g1_w2, g1_b2, p_h1);
    // conv2
    k_agg128<<<(N + 7) / 8, 256>>>(p_h1, p_zbuf, N);
    k_mma_mlp<<<148, 256, MMA_SMEM>>>(p_zbuf, HID, 5, N, 16,
                                      g2_w1, 128, g2_b1, g2_w2, g2_b2, p_h2);
    // conv3
    k_agg128<<<(N + 7) / 8, 256>>>(p_h2, p_zbuf, N);
    k_mma_mlp<<<148, 256, MMA_SMEM>>>(p_zbuf, HID, 5, N, 16,
                                      g3_w1, 128, g3_b1, g3_w2, g3_b2, p_h3);

    // pool-first JK: segment_sum then tiny GEMMs
    k_pool<<<G_N, 128>>>(p_h1, p_h2, p_h3);
    k_smallmm<<<G_N / 8, 128>>>(p_pooled, 384, jk_w, jk_b, 1, p_grow);
    k_smallmm<<<G_N / 8, 128>>>(p_grow, 128, c1_w, c1_b, 0, p_zc);

    // batch norm + classifier head
    k_bn<<<HID, 256>>>();
    k_final<<<G_N, 128>>>(bn_g, bn_b, c2_w, c2_b, out);
}